// round 13
// baseline (speedup 1.0000x reference)
#include <cuda_runtime.h>
#include <stdint.h>
#include <math.h>

#define NQ   12
#define NL   6
#define NC   64
#define TPB  128
#define STU  17                    // u64 stride per row per plane (odd -> conflict-free)
#define STF  34                    // float stride per row per plane
#define PLANEU (TPB * STU)         // 2176 u64 per plane
#define SMEMU (2 * PLANEU)         // R plane + I plane

typedef unsigned long long u64;
#define SGN2  0x8000000080000000ULL
#define SGNHI 0x8000000000000000ULL

// Amp i[11:0], wire w = bit 11-w. 32 amps/thread: reg p = k>>1, pair-lane = k&1.
// L0: k = i[4:0] (wires 7-11), tid = i[11:5].
// L1: k = i[9:5] (wires 2-6),  tid = (i[4:0]<<2) | i[11:10]; reg q = i[9:6], pair = i[5].
// Layer 0 RX folded into AngleEmbedding (angles add); init built directly in L1.
// sigma round: L1 -> L0 applying the CNOT ring. Layers 1..5: X1 (L0->L1), gates, X2 (sigma).
// Final layer: X2 skipped; ring folded into readout parity masks.

extern __shared__ u64 dynsm[];     // [2][PLANEU]

__device__ __forceinline__ u64 bc2(float c){ u64 r; asm("mov.b64 %0, {%1, %1};" : "=l"(r) : "f"(c)); return r; }
__device__ __forceinline__ u64 pk2(float lo, float hi){ u64 r; asm("mov.b64 %0, {%1, %2};" : "=l"(r) : "f"(lo), "f"(hi)); return r; }
__device__ __forceinline__ float lo32(u64 v){ float f; asm("{ .reg .f32 h; mov.b64 {%0, h}, %1; }" : "=f"(f) : "l"(v)); return f; }
__device__ __forceinline__ float hi32(u64 v){ float f; asm("{ .reg .f32 l; mov.b64 {l, %0}, %1; }" : "=f"(f) : "l"(v)); return f; }
__device__ __forceinline__ u64 swap2(u64 v){ u64 r; asm("{ .reg .f32 l, h; mov.b64 {l, h}, %1; mov.b64 %0, {h, l}; }" : "=l"(r) : "l"(v)); return r; }
__device__ __forceinline__ u64 mul2(u64 a, u64 b){ u64 r; asm("mul.rn.f32x2 %0, %1, %2;" : "=l"(r) : "l"(a), "l"(b)); return r; }
__device__ __forceinline__ u64 fma2(u64 a, u64 b, u64 c){ u64 r; asm("fma.rn.f32x2 %0, %1, %2, %3;" : "=l"(r) : "l"(a), "l"(b), "l"(c)); return r; }
__device__ __forceinline__ u64 add2(u64 a, u64 b){ u64 r; asm("add.rn.f32x2 %0, %1, %2;" : "=l"(r) : "l"(a), "l"(b)); return r; }
__device__ __forceinline__ u64 rxh(u64 C2, u64 S2, u64 T, u64 U){ return fma2(C2, T, mul2(S2, U)); }

// RX on a cross-register wire (packed mask mp) over 16-reg planes
__device__ __forceinline__ void rx_gate(u64* R, u64* I, float c, float s, int mp)
{
    const u64 C2 = bc2(c), S2 = bc2(s), N2 = S2 ^ SGN2;
#pragma unroll
    for (int p0 = 0; p0 < 16; ++p0) {
        if (p0 & mp) continue;
        const int p1 = p0 | mp;
        const u64 r0 = R[p0], i0 = I[p0], r1 = R[p1], i1 = I[p1];
        R[p0] = rxh(C2, S2, r0, i1);
        I[p0] = rxh(C2, N2, i0, r1);
        R[p1] = rxh(C2, S2, r1, i0);
        I[p1] = rxh(C2, N2, i1, r0);
    }
}

// RX on the in-register pair-lane wire via lane-swapped f32x2 (4 fma-pipe ops/reg)
__device__ __forceinline__ void rx_lane(u64* R, u64* I, float c, float s)
{
    const u64 C2 = bc2(c), S2 = bc2(s), N2 = S2 ^ SGN2;
#pragma unroll
    for (int p = 0; p < 16; ++p) {
        const u64 Rs = swap2(R[p]), Is = swap2(I[p]);
        R[p] = rxh(C2, S2, R[p], Is);
        I[p] = rxh(C2, N2, I[p], Rs);
    }
}

// RX on a lane-bit wire via warp shuffle (lane mask lm); RX update is role-symmetric
__device__ __forceinline__ void rx_shfl(u64* R, u64* I, float c, float s, int lm)
{
    const u64 C2 = bc2(c), S2 = bc2(s), N2 = S2 ^ SGN2;
#pragma unroll
    for (int p = 0; p < 16; ++p) {
        const u64 Rp = __shfl_xor_sync(0xffffffffu, R[p], lm);
        const u64 Ip = __shfl_xor_sync(0xffffffffu, I[p], lm);
        R[p] = rxh(C2, S2, R[p], Ip);
        I[p] = rxh(C2, N2, I[p], Rp);
    }
}

__global__ __launch_bounds__(TPB, 4)
void qnn_kernel(const float* __restrict__ x,
                const float* __restrict__ qw,
                const float* __restrict__ W,
                const float* __restrict__ bias,
                float* __restrict__ out)
{
    __shared__ float cx[NQ], sx[NQ];        // combined embedding + layer-0 half-angles
    __shared__ float cq[NL * NQ], sq[NL * NQ];
    __shared__ float red[4][NQ];
    __shared__ float zf[NQ];

    u64*   const bRu = dynsm;
    u64*   const bIu = dynsm + PLANEU;
    float* const bRf = (float*)bRu;
    float* const bIf = (float*)bIu;

    const int tid  = threadIdx.x;
    const int bsmp = blockIdx.x;
    const int lane = tid & 31;
    const int warp = tid >> 5;

    if (tid < NQ) {
        float s, c;
        sincosf(0.5f * (x[bsmp * NQ + tid] + qw[tid]), &s, &c);   // RX(x)·RX(qw0) = RX(x+qw0)
        cx[tid] = c; sx[tid] = s;
    }
    if (tid >= 32 && tid < 32 + NL * NQ) {
        const int idx = tid - 32;
        float s, c;
        sincosf(0.5f * qw[idx], &s, &c);
        cq[idx] = c; sq[idx] = s;
    }
    __syncthreads();

    // ---- X2/sigma gather offsets (L1 store -> L0 regs), from L0 amp indexing ----
    u64 R[16], I[16];
    uint32_t off3p[16];                // 32 offsets (2x u16)
    const int base = tid << 5;

#pragma unroll
    for (int k = 0; k < 32; ++k) {
        // sigma(i): CNOT-ring gather source j (new[i] = old[j]); address under L1 store
        int j = base | k;
#pragma unroll
        for (int w = NQ - 1; w >= 0; --w) {
            const int t  = (w + 1) % NQ;
            const int bc = (j >> (11 - w)) & 1;
            j ^= bc << (11 - t);
        }
        const uint32_t row1 = (uint32_t)(((j & 31) << 2) | ((j >> 10) & 3));   // L1 tid of j
        const uint32_t off  = row1 * STF + ((j >> 5) & 31);                    // float index
        if (k & 1) off3p[k >> 1] |= off << 16;
        else       off3p[k >> 1]  = off;
    }

    // ---- init: fused AngleEmbedding+layer0 product state, built in L1 layout ----
#pragma unroll
    for (int p = 0; p < 16; ++p) {
        float re2[2], im2[2];
#pragma unroll
        for (int pr = 0; pr < 2; ++pr) {
            const int i = ((tid & 3) << 10) | ((((p << 1) | pr)) << 5) | (tid >> 2);
            float mag = 1.0f;
#pragma unroll
            for (int w = 0; w < NQ; ++w)
                mag *= ((i >> (11 - w)) & 1) ? sx[w] : cx[w];
            const int pc = __popc(i) & 3;          // amp = mag * (-i)^popcount
            re2[pr] = (pc == 0) ? mag : (pc == 2) ? -mag : 0.f;
            im2[pr] = (pc == 1) ? -mag : (pc == 3) ? mag : 0.f;
        }
        R[p] = pk2(re2[0], re2[1]);
        I[p] = pk2(im2[0], im2[1]);
    }

    const int xsw    = (tid >> 5) << 2;                                 // X1 store col swizzle (u64)
    const int stbase = tid * STU;                                       // own-row u64 store base
    const int x1b    = ((tid & 3) << 5) * STF + ((tid >> 2) ^ ((tid & 3) << 3));

    // ---- layer-0 sigma round: L1 -> L0 (applies the ring CNOTs of layer 0) ----
#pragma unroll
    for (int p = 0; p < 16; ++p) { bRu[stbase + p] = R[p]; bIu[stbase + p] = I[p]; }
    __syncthreads();
#pragma unroll
    for (int q = 0; q < 16; ++q) {
        const int o0 = off3p[q] & 0xFFFF;
        const int o1 = off3p[q] >> 16;
        R[q] = pk2(bRf[o0], bRf[o1]);
        I[q] = pk2(bIf[o0], bIf[o1]);
    }

    // ---- entangler layers 1..5 ----
#pragma unroll 1
    for (int l = 1; l < NL; ++l) {
        const float* cl = &cq[l * NQ];
        const float* sl = &sq[l * NQ];

        // L0 gates: wires 7-10 cross, wire 11 pair-lane
        rx_gate(R, I, cl[7],  sl[7],  8);
        rx_gate(R, I, cl[8],  sl[8],  4);
        rx_gate(R, I, cl[9],  sl[9],  2);
        rx_gate(R, I, cl[10], sl[10], 1);
        rx_lane(R, I, cl[11], sl[11]);

        // X1: L0 -> L1 (swizzled store, cross-warp gather)
        __syncthreads();
#pragma unroll
        for (int p = 0; p < 16; ++p) {
            const int a = stbase + (p ^ xsw);
            bRu[a] = R[p]; bIu[a] = I[p];
        }
        __syncthreads();
#pragma unroll
        for (int q = 0; q < 16; ++q) {
            const int a0 = x1b + (2 * q) * STF, a1 = a0 + STF;
            R[q] = pk2(bRf[a0], bRf[a1]);
            I[q] = pk2(bIf[a0], bIf[a1]);
        }

        // L1 gates: wires 2-5 cross, wire 6 pair-lane, wires 0-1 lane-shuffle
        rx_gate(R, I, cl[2], sl[2], 8);
        rx_gate(R, I, cl[3], sl[3], 4);
        rx_gate(R, I, cl[4], sl[4], 2);
        rx_gate(R, I, cl[5], sl[5], 1);
        rx_lane(R, I, cl[6], sl[6]);
        rx_shfl(R, I, cl[0], sl[0], 2);     // wire 0 = bit11 = lane bit 1
        rx_shfl(R, I, cl[1], sl[1], 1);     // wire 1 = bit10 = lane bit 0

        // X2: fused CNOT-ring permutation, L1 -> L0 (skipped on final layer)
        if (l < NL - 1) {
            __syncthreads();
#pragma unroll
            for (int p = 0; p < 16; ++p) { bRu[stbase + p] = R[p]; bIu[stbase + p] = I[p]; }
            __syncthreads();
#pragma unroll
            for (int q = 0; q < 16; ++q) {
                const int o0 = off3p[q] & 0xFFFF;
                const int o1 = off3p[q] >> 16;
                R[q] = pk2(bRf[o0], bRf[o1]);
                I[q] = pk2(bIf[o0], bIf[o1]);
            }
        }
    }

    // ---- readout in L1 layout, final ring folded into parity masks ----
    // <Z_w> = sum_j (-1)^{wire_w(f(j))} |psi(j)|^2.
    // Reg parts over (q = wires 2-5, pair = wire 6):
    //   S1: none; S2: q3; S3: q3^q2; S4: q3^q2^q1; S5: parity(q); S6: parity(q)^pair.
    u64 S1 = 0ull, S2 = 0ull, S3 = 0ull, S4 = 0ull, S5 = 0ull, S6 = 0ull;
#pragma unroll
    for (int q = 0; q < 16; ++q) {
        const u64 P  = fma2(R[q], R[q], mul2(I[q], I[q]));
        const u64 Ph = P ^ SGNHI;                         // pair=1 (hi lane) negated
        S1 = add2(S1, P);
        S2 = add2(S2, (q & 8) ? (P ^ SGN2) : P);
        S3 = add2(S3, (((q >> 3) ^ (q >> 2)) & 1) ? (P ^ SGN2) : P);
        S4 = add2(S4, (((q >> 3) ^ (q >> 2) ^ (q >> 1)) & 1) ? (P ^ SGN2) : P);
        const int pq = __popc(q) & 1;
        S5 = add2(S5, pq ? (P ^ SGN2) : P);
        S6 = add2(S6, pq ? (Ph ^ SGN2) : Ph);
    }
    const float t1 = lo32(S1) + hi32(S1);
    const float t2 = lo32(S2) + hi32(S2);
    const float t3 = lo32(S3) + hi32(S3);
    const float t4 = lo32(S4) + hi32(S4);
    const float t5 = lo32(S5) + hi32(S5);
    const float t6 = lo32(S6) + hi32(S6);

    // thread bits: tid[1:0] = wires 0,1; tid[6:2] = wires 7..11 (bit6 = wire7 ... bit2 = wire11)
    const int w0 = (tid >> 1) & 1, w1 = tid & 1;
    const int b  = tid >> 2;
    const int pl = __popc(b) & 1;                  // parity wires 7-11

    float z12[NQ];
    const int s01 = (w0 ^ w1) & 1;
    z12[1] = s01 ? -t1 : t1;
    z12[2] = s01 ? -t2 : t2;
    z12[3] = s01 ? -t3 : t3;
    z12[4] = s01 ? -t4 : t4;
    z12[5] = s01 ? -t5 : t5;
    z12[6] = s01 ? -t6 : t6;
    z12[0] = ((w1 ^ pl) & 1) ? -t6 : t6;           // wires 1..11
    int acc = s01;
    acc ^= (b >> 4) & 1; z12[7]  = (acc & 1) ? -t6 : t6;   // + wire7
    acc ^= (b >> 3) & 1; z12[8]  = (acc & 1) ? -t6 : t6;   // + wire8
    acc ^= (b >> 2) & 1; z12[9]  = (acc & 1) ? -t6 : t6;   // + wire9
    acc ^= (b >> 1) & 1; z12[10] = (acc & 1) ? -t6 : t6;   // + wire10
    acc ^= b & 1;        z12[11] = (acc & 1) ? -t6 : t6;   // + wire11

#pragma unroll
    for (int w = 0; w < NQ; ++w) {
#pragma unroll
        for (int o = 16; o > 0; o >>= 1)
            z12[w] += __shfl_xor_sync(0xffffffffu, z12[w], o);
    }
    if (lane == 0) {
#pragma unroll
        for (int w = 0; w < NQ; ++w) red[warp][w] = z12[w];
    }
    __syncthreads();
    if (tid < NQ)
        zf[tid] = red[0][tid] + red[1][tid] + red[2][tid] + red[3][tid];
    __syncthreads();

    // ---- classifier head ----
    if (tid < NC) {
        float acc2 = bias[tid];
#pragma unroll
        for (int w = 0; w < NQ; ++w)
            acc2 = fmaf(zf[w], W[tid * NQ + w], acc2);
        out[bsmp * NC + tid] = acc2;
    }
}

extern "C" void kernel_launch(void* const* d_in, const int* in_sizes, int n_in,
                              void* d_out, int out_size)
{
    const float* x  = (const float*)d_in[0];   // (512, 12)
    const float* qw = (const float*)d_in[1];   // (6, 12)
    const float* W  = (const float*)d_in[2];   // (64, 12)
    const float* bs = (const float*)d_in[3];   // (64,)
    float* out = (float*)d_out;                // (512, 64)

    const int smem = SMEMU * (int)sizeof(u64);   // 34816 B
    cudaFuncSetAttribute(qnn_kernel, cudaFuncAttributeMaxDynamicSharedMemorySize, smem);
    qnn_kernel<<<512, TPB, smem>>>(x, qw, W, bs, out);
}

// round 15
// speedup vs baseline: 1.6769x; 1.6769x over previous
#include <cuda_runtime.h>
#include <stdint.h>
#include <math.h>

#define NQ   12
#define NL   6
#define NC   64
#define TPB  128
#define STU  17                    // u64 stride per row per plane (odd -> conflict-free)
#define STF  34                    // float stride per row per plane
#define PLANEU (TPB * STU)         // 2176 u64 per plane
#define SMEMU (2 * PLANEU)         // R plane + I plane

typedef unsigned long long u64;
#define SGN2  0x8000000080000000ULL
#define SGNHI 0x8000000000000000ULL

// Amp i[11:0], wire w = bit 11-w. 32 amps/thread: reg p = k>>1, pair-lane = k&1.
// L0: k = i[4:0] (wires 7-11), tid = i[11:5].
// L1: k = i[9:5] (wires 2-6),  tid = (i[4:0]<<2) | i[11:10]; reg q = i[9:6], pair = i[5].
// Layer 0: RX folded into embedding (angles add); its ring permutation applied at INIT
// by evaluating the product state at sigma(i) (product state -> direct evaluation).
// Layers 1..5: L0 gates, X1 (L0->L1), L1 gates, X2 = sigma (skipped on final layer;
// final ring folded into readout parity masks).

extern __shared__ u64 dynsm[];     // [2][PLANEU]

__device__ __forceinline__ u64 bc2(float c){ u64 r; asm("mov.b64 %0, {%1, %1};" : "=l"(r) : "f"(c)); return r; }
__device__ __forceinline__ u64 pk2(float lo, float hi){ u64 r; asm("mov.b64 %0, {%1, %2};" : "=l"(r) : "f"(lo), "f"(hi)); return r; }
__device__ __forceinline__ float lo32(u64 v){ float f; asm("{ .reg .f32 h; mov.b64 {%0, h}, %1; }" : "=f"(f) : "l"(v)); return f; }
__device__ __forceinline__ float hi32(u64 v){ float f; asm("{ .reg .f32 l; mov.b64 {l, %0}, %1; }" : "=f"(f) : "l"(v)); return f; }
__device__ __forceinline__ u64 mul2(u64 a, u64 b){ u64 r; asm("mul.rn.f32x2 %0, %1, %2;" : "=l"(r) : "l"(a), "l"(b)); return r; }
__device__ __forceinline__ u64 fma2(u64 a, u64 b, u64 c){ u64 r; asm("fma.rn.f32x2 %0, %1, %2, %3;" : "=l"(r) : "l"(a), "l"(b), "l"(c)); return r; }
__device__ __forceinline__ u64 add2(u64 a, u64 b){ u64 r; asm("add.rn.f32x2 %0, %1, %2;" : "=l"(r) : "l"(a), "l"(b)); return r; }
__device__ __forceinline__ u64 rxh(u64 C2, u64 S2, u64 T, u64 U){ return fma2(C2, T, mul2(S2, U)); }

// RX on a cross-register wire (packed mask mp) over 16-reg planes
__device__ __forceinline__ void rx_gate(u64* R, u64* I, float c, float s, int mp)
{
    const u64 C2 = bc2(c), S2 = bc2(s), N2 = S2 ^ SGN2;
#pragma unroll
    for (int p0 = 0; p0 < 16; ++p0) {
        if (p0 & mp) continue;
        const int p1 = p0 | mp;
        const u64 r0 = R[p0], i0 = I[p0], r1 = R[p1], i1 = I[p1];
        R[p0] = rxh(C2, S2, r0, i1);
        I[p0] = rxh(C2, N2, i0, r1);
        R[p1] = rxh(C2, S2, r1, i0);
        I[p1] = rxh(C2, N2, i1, r0);
    }
}

// RX on the in-register pair-lane wire (scalar lanes)
__device__ __forceinline__ void rx_lane(u64* R, u64* I, float c, float s)
{
#pragma unroll
    for (int p = 0; p < 16; ++p) {
        const float rx = lo32(R[p]), ry = hi32(R[p]);
        const float ix = lo32(I[p]), iy = hi32(I[p]);
        R[p] = pk2(fmaf(c, rx,  s * iy), fmaf(c, ry,  s * ix));
        I[p] = pk2(fmaf(c, ix, -s * ry), fmaf(c, iy, -s * rx));
    }
}

// RX on a lane-bit wire via warp shuffle (lane mask lm); RX update is role-symmetric
__device__ __forceinline__ void rx_shfl(u64* R, u64* I, float c, float s, int lm)
{
    const u64 C2 = bc2(c), S2 = bc2(s), N2 = S2 ^ SGN2;
#pragma unroll
    for (int p = 0; p < 16; ++p) {
        const u64 Rp = __shfl_xor_sync(0xffffffffu, R[p], lm);
        const u64 Ip = __shfl_xor_sync(0xffffffffu, I[p], lm);
        R[p] = rxh(C2, S2, R[p], Ip);
        I[p] = rxh(C2, N2, I[p], Rp);
    }
}

__global__ __launch_bounds__(TPB, 4)
void qnn_kernel(const float* __restrict__ x,
                const float* __restrict__ qw,
                const float* __restrict__ W,
                const float* __restrict__ bias,
                float* __restrict__ out)
{
    __shared__ float cx[NQ], sx[NQ];        // embedding + layer-0 combined half-angles
    __shared__ float cq[NL * NQ], sq[NL * NQ];
    __shared__ float red[4][NQ];
    __shared__ float zf[NQ];

    u64*   const bRu = dynsm;
    u64*   const bIu = dynsm + PLANEU;
    float* const bRf = (float*)bRu;
    float* const bIf = (float*)bIu;

    const int tid  = threadIdx.x;
    const int bsmp = blockIdx.x;
    const int lane = tid & 31;
    const int warp = tid >> 5;

    if (tid < NQ) {
        float s, c;
        sincosf(0.5f * (x[bsmp * NQ + tid] + qw[tid]), &s, &c);   // RX(x)·RX(qw0) = RX(x+qw0)
        cx[tid] = c; sx[tid] = s;
    }
    if (tid >= 32 && tid < 32 + NL * NQ) {
        const int idx = tid - 32;
        float s, c;
        sincosf(0.5f * qw[idx], &s, &c);
        cq[idx] = c; sq[idx] = s;
    }
    __syncthreads();

    // ---- init (L0): layer-0 ring applied analytically -> evaluate product state at sigma(i) ----
    u64 R[16], I[16];
    uint32_t off3p[16];                // 32 X2 offsets (2x u16)
    const int base = tid << 5;

#pragma unroll
    for (int k = 0; k < 32; ++k) {
        // sigma(i): CNOT-ring source j (new[i] = old[j])
        int j = base | k;
#pragma unroll
        for (int w = NQ - 1; w >= 0; --w) {
            const int t  = (w + 1) % NQ;
            const int bc = (j >> (11 - w)) & 1;
            j ^= bc << (11 - t);
        }

        // amp = product-state amplitude at j (combined embedding+layer0 angles)
        float mag = 1.0f;
#pragma unroll
        for (int w = 0; w < NQ; ++w)
            mag *= ((j >> (11 - w)) & 1) ? sx[w] : cx[w];
        const int pc = __popc(j) & 3;  // amp = mag * (-i)^popcount(j)
        float re = 0.f, im = 0.f;
        if      (pc == 0) re =  mag;
        else if (pc == 1) im = -mag;
        else if (pc == 2) re = -mag;
        else              im =  mag;

        if (k & 1) { R[k >> 1] = pk2(lo32(R[k >> 1]), re); I[k >> 1] = pk2(lo32(I[k >> 1]), im); }
        else       { R[k >> 1] = pk2(re, 0.f);             I[k >> 1] = pk2(im, 0.f); }

        // X2 gather offset for later layers: address of j under the L1 store layout
        const uint32_t row1 = (uint32_t)(((j & 31) << 2) | ((j >> 10) & 3));   // L1 tid of j
        const uint32_t off  = row1 * STF + ((j >> 5) & 31);                    // float index
        if (k & 1) off3p[k >> 1] |= off << 16;
        else       off3p[k >> 1]  = off;
    }

    const int xsw    = (tid >> 5) << 2;                                 // X1 store col swizzle (u64)
    const int stbase = tid * STU;                                       // own-row u64 store base
    const int x1b    = ((tid & 3) << 5) * STF + ((tid >> 2) ^ ((tid & 3) << 3));

    // ---- entangler layers 1..5 ----
#pragma unroll 1
    for (int l = 1; l < NL; ++l) {
        const float* cl = &cq[l * NQ];
        const float* sl = &sq[l * NQ];

        // L0 gates: wires 7-10 cross, wire 11 pair-lane
        rx_gate(R, I, cl[7],  sl[7],  8);
        rx_gate(R, I, cl[8],  sl[8],  4);
        rx_gate(R, I, cl[9],  sl[9],  2);
        rx_gate(R, I, cl[10], sl[10], 1);
        rx_lane(R, I, cl[11], sl[11]);

        // X1: L0 -> L1 (swizzled store, cross-warp gather)
        if (l > 1) __syncthreads();
#pragma unroll
        for (int p = 0; p < 16; ++p) {
            const int a = stbase + (p ^ xsw);
            bRu[a] = R[p]; bIu[a] = I[p];
        }
        __syncthreads();
#pragma unroll
        for (int q = 0; q < 16; ++q) {
            const int a0 = x1b + (2 * q) * STF, a1 = a0 + STF;
            R[q] = pk2(bRf[a0], bRf[a1]);
            I[q] = pk2(bIf[a0], bIf[a1]);
        }

        // L1 gates: wires 2-5 cross, wire 6 pair-lane, wires 0-1 lane-shuffle
        rx_gate(R, I, cl[2], sl[2], 8);
        rx_gate(R, I, cl[3], sl[3], 4);
        rx_gate(R, I, cl[4], sl[4], 2);
        rx_gate(R, I, cl[5], sl[5], 1);
        rx_lane(R, I, cl[6], sl[6]);
        rx_shfl(R, I, cl[0], sl[0], 2);     // wire 0 = bit11 = lane bit 1
        rx_shfl(R, I, cl[1], sl[1], 1);     // wire 1 = bit10 = lane bit 0

        // X2: fused CNOT-ring permutation, L1 -> L0 (skipped on final layer)
        if (l < NL - 1) {
            __syncthreads();
#pragma unroll
            for (int p = 0; p < 16; ++p) { bRu[stbase + p] = R[p]; bIu[stbase + p] = I[p]; }
            __syncthreads();
#pragma unroll
            for (int q = 0; q < 16; ++q) {
                const int o0 = off3p[q] & 0xFFFF;
                const int o1 = off3p[q] >> 16;
                R[q] = pk2(bRf[o0], bRf[o1]);
                I[q] = pk2(bIf[o0], bIf[o1]);
            }
        }
    }

    // ---- readout in L1 layout, final ring folded into parity masks ----
    // <Z_w> = sum_j (-1)^{wire_w(f(j))} |psi(j)|^2.
    // Reg parts over (q = wires 2-5, pair = wire 6):
    //   S1: none; S2: q3; S3: q3^q2; S4: q3^q2^q1; S5: parity(q); S6: parity(q)^pair.
    u64 S1 = 0ull, S2 = 0ull, S3 = 0ull, S4 = 0ull, S5 = 0ull, S6 = 0ull;
#pragma unroll
    for (int q = 0; q < 16; ++q) {
        const u64 P  = fma2(R[q], R[q], mul2(I[q], I[q]));
        const u64 Ph = P ^ SGNHI;                         // pair=1 (hi lane) negated
        S1 = add2(S1, P);
        S2 = add2(S2, (q & 8) ? (P ^ SGN2) : P);
        S3 = add2(S3, (((q >> 3) ^ (q >> 2)) & 1) ? (P ^ SGN2) : P);
        S4 = add2(S4, (((q >> 3) ^ (q >> 2) ^ (q >> 1)) & 1) ? (P ^ SGN2) : P);
        const int pq = __popc(q) & 1;
        S5 = add2(S5, pq ? (P ^ SGN2) : P);
        S6 = add2(S6, pq ? (Ph ^ SGN2) : Ph);
    }
    const float t1 = lo32(S1) + hi32(S1);
    const float t2 = lo32(S2) + hi32(S2);
    const float t3 = lo32(S3) + hi32(S3);
    const float t4 = lo32(S4) + hi32(S4);
    const float t5 = lo32(S5) + hi32(S5);
    const float t6 = lo32(S6) + hi32(S6);

    // thread bits: tid[1:0] = wires 0,1; tid[6:2] = wires 7..11 (bit6 = wire7 ... bit2 = wire11)
    const int w0 = (tid >> 1) & 1, w1 = tid & 1;
    const int b  = tid >> 2;
    const int pl = __popc(b) & 1;                  // parity wires 7-11

    float z12[NQ];
    const int s01 = (w0 ^ w1) & 1;
    z12[1] = s01 ? -t1 : t1;
    z12[2] = s01 ? -t2 : t2;
    z12[3] = s01 ? -t3 : t3;
    z12[4] = s01 ? -t4 : t4;
    z12[5] = s01 ? -t5 : t5;
    z12[6] = s01 ? -t6 : t6;
    z12[0] = ((w1 ^ pl) & 1) ? -t6 : t6;           // wires 1..11
    int acc = s01;
    acc ^= (b >> 4) & 1; z12[7]  = (acc & 1) ? -t6 : t6;   // + wire7
    acc ^= (b >> 3) & 1; z12[8]  = (acc & 1) ? -t6 : t6;   // + wire8
    acc ^= (b >> 2) & 1; z12[9]  = (acc & 1) ? -t6 : t6;   // + wire9
    acc ^= (b >> 1) & 1; z12[10] = (acc & 1) ? -t6 : t6;   // + wire10
    acc ^= b & 1;        z12[11] = (acc & 1) ? -t6 : t6;   // + wire11

#pragma unroll
    for (int w = 0; w < NQ; ++w) {
#pragma unroll
        for (int o = 16; o > 0; o >>= 1)
            z12[w] += __shfl_xor_sync(0xffffffffu, z12[w], o);
    }
    if (lane == 0) {
#pragma unroll
        for (int w = 0; w < NQ; ++w) red[warp][w] = z12[w];
    }
    __syncthreads();
    if (tid < NQ)
        zf[tid] = red[0][tid] + red[1][tid] + red[2][tid] + red[3][tid];
    __syncthreads();

    // ---- classifier head ----
    if (tid < NC) {
        float acc2 = bias[tid];
#pragma unroll
        for (int w = 0; w < NQ; ++w)
            acc2 = fmaf(zf[w], W[tid * NQ + w], acc2);
        out[bsmp * NC + tid] = acc2;
    }
}

extern "C" void kernel_launch(void* const* d_in, const int* in_sizes, int n_in,
                              void* d_out, int out_size)
{
    const float* x  = (const float*)d_in[0];   // (512, 12)
    const float* qw = (const float*)d_in[1];   // (6, 12)
    const float* W  = (const float*)d_in[2];   // (64, 12)
    const float* bs = (const float*)d_in[3];   // (64,)
    float* out = (float*)d_out;                // (512, 64)

    const int smem = SMEMU * (int)sizeof(u64);   // 34816 B
    cudaFuncSetAttribute(qnn_kernel, cudaFuncAttributeMaxDynamicSharedMemorySize, smem);
    qnn_kernel<<<512, TPB, smem>>>(x, qw, W, bs, out);
}